// round 2
// baseline (speedup 1.0000x reference)
#include <cuda_runtime.h>

#define T_N 1024
#define B_N 256
#define H_N 20
#define B3  (B_N * 3)
#define OFF (T_N * B3)

// MLP output (memory kernel me[T]) — __device__ global scratch, no allocation.
__device__ float g_me[T_N];

// ---------------------------------------------------------------------------
// Kernel A: me[i] = sigmoid(MLP(t[i]))
// ---------------------------------------------------------------------------
__global__ void mlp_kernel(const float* __restrict__ t,
                           const float* __restrict__ w1, const float* __restrict__ b1,
                           const float* __restrict__ w2, const float* __restrict__ b2,
                           const float* __restrict__ w3, const float* __restrict__ b3,
                           const float* __restrict__ w4, const float* __restrict__ b4) {
    int i = blockIdx.x * blockDim.x + threadIdx.x;
    if (i >= T_N) return;
    float tv = t[i];

    float h1[H_N], h2[H_N];
    #pragma unroll
    for (int o = 0; o < H_N; o++)
        h1[o] = tanhf(tv * w1[o] + b1[o]);

    #pragma unroll
    for (int o = 0; o < H_N; o++) {
        float acc = b2[o];
        #pragma unroll
        for (int m = 0; m < H_N; m++)
            acc += h1[m] * w2[m * H_N + o];
        h2[o] = tanhf(acc);
    }

    #pragma unroll
    for (int o = 0; o < H_N; o++) {
        float acc = b3[o];
        #pragma unroll
        for (int m = 0; m < H_N; m++)
            acc += h2[m] * w3[m * H_N + o];
        h1[o] = tanhf(acc);
    }

    float acc = b4[0];
    #pragma unroll
    for (int m = 0; m < H_N; m++)
        acc += h1[m] * w4[m];

    g_me[i] = 1.0f / (1.0f + expf(-acc));
}

// ---------------------------------------------------------------------------
// Kernel B: blocked-scatter sequential scan.
// One CTA (128 thr) per batch element.
//   warp 0      : sequential stepper. Lane l owns window accumulators
//                 A_cur (step 32m+l of current block) and A_next (next block).
//                 Per step: 1 shfl broadcast, redundant state update, 2-FFMA scatter.
//   warps 1..3  : during block m, precompute P_{m+1}[l] = sum_{k<32m} rs[32(m+1)+l-k]*Ih[k]
// rs[i] = me[T-i]  (reversed kernel), so integ_j = dt * sum_{k<j} rs[j-k]*Ih[k].
// ---------------------------------------------------------------------------
__global__ void __launch_bounds__(128) scan_kernel(
    const float* __restrict__ t,
    const float* __restrict__ y,
    const float* __restrict__ beta_p,
    const float* __restrict__ gamma_p,
    float* __restrict__ out) {

    __shared__ float rs[T_N];          // reversed memory kernel
    __shared__ float Ih[T_N];          // I history
    __shared__ float Pbuf[2][3][32];   // double-buffered far-history partials

    const int b    = blockIdx.x;
    const int tid  = threadIdx.x;
    const int warp = tid >> 5;
    const int lane = tid & 31;

    // init shared
    for (int i = tid; i < T_N; i += 128)
        rs[i] = (i == 0) ? 0.0f : g_me[T_N - i];
    for (int i = tid; i < 192; i += 128)
        (&Pbuf[0][0][0])[i] = 0.0f;

    const float dt    = t[0] - t[1];
    const float beta  = beta_p[0];
    const float gamma = gamma_p[0];

    __syncthreads();

    if (warp == 0) {
        // ------------------ sequential stepper ------------------
        float S = y[b * 3 + 0];
        float I = y[b * 3 + 1];
        float R = y[b * 3 + 2];
        float A_cur = 0.0f, A_next = 0.0f;
        const int b3 = b * 3;

        for (int m = 0; m < 32; m++) {
            #pragma unroll 4
            for (int p = 0; p < 32; p++) {
                const int j = (m << 5) + p;
                float Iv;
                if (j == 0) {
                    Iv = I;
                    if (lane == 0) {
                        Ih[0] = Iv;
                        out[b3 + 0] = S;
                        out[b3 + 1] = I;
                        out[b3 + 2] = R;
                        const int zb = OFF + (T_N - 1) * B3 + b3;
                        out[zb + 0] = 0.0f;
                        out[zb + 1] = 0.0f;
                        out[zb + 2] = 0.0f;
                    }
                } else {
                    // independent of integ — issue before the shfl lands
                    const float bSI = beta * S * I;
                    const float gI  = gamma * I;
                    const float d1  = bSI - gI;
                    const float In  = I + d1 * dt;

                    const float a     = __shfl_sync(0xffffffffu, A_cur, p);
                    const float integ = dt * a;
                    const float d0    = integ - bSI;
                    const float d2    = gI - integ;
                    S += d0 * dt;
                    R += d2 * dt;
                    I  = In;
                    Iv = In;

                    if (lane == 0) Ih[j] = In;

                    // lanes 0-5 write solution[j] and diff[j-1] in one STG
                    float v = (lane == 0) ? S :
                              (lane == 1) ? I :
                              (lane == 2) ? R :
                              (lane == 3) ? d0 :
                              (lane == 4) ? d1 : d2;
                    int idx = (lane < 3) ? (j * B3 + b3 + lane)
                                         : (OFF + (j - 1) * B3 + b3 + lane - 3);
                    if (lane < 6) out[idx] = v;
                }

                // scatter I_j into the near-history window
                const int dlt = lane - p;
                if (dlt > 0) A_cur += rs[dlt] * Iv;
                A_next += rs[dlt + 32] * Iv;
            }

            __syncthreads();   // block boundary: Ih visible, Pbuf ready

            if (m < 31) {
                const int par = (m + 1) & 1;
                A_cur  = A_next + Pbuf[par][0][lane]
                                + Pbuf[par][1][lane]
                                + Pbuf[par][2][lane];
                A_next = 0.0f;
            }
        }
    } else {
        // ------------------ far-history helpers ------------------
        const int w = warp - 1;   // 0..2
        for (int m = 0; m < 32; m++) {
            if (m >= 1 && m < 31) {
                const int Kend = m << 5;           // k < 32m (ready: blocks <= m-1)
                const int J    = (m + 1) << 5;     // target block start
                const int base = J + lane;
                float acc = 0.0f;
                #pragma unroll 4
                for (int k = w; k < Kend; k += 3)
                    acc += rs[base - k] * Ih[k];
                Pbuf[(m + 1) & 1][w][lane] = acc;
            }
            __syncthreads();
        }
    }
}

// ---------------------------------------------------------------------------
// Launch
// ---------------------------------------------------------------------------
extern "C" void kernel_launch(void* const* d_in, const int* in_sizes, int n_in,
                              void* d_out, int out_size) {
    const float* t     = (const float*)d_in[0];
    const float* y     = (const float*)d_in[1];
    const float* w1    = (const float*)d_in[2];
    const float* b1    = (const float*)d_in[3];
    const float* w2    = (const float*)d_in[4];
    const float* b2    = (const float*)d_in[5];
    const float* w3    = (const float*)d_in[6];
    const float* b3    = (const float*)d_in[7];
    const float* w4    = (const float*)d_in[8];
    const float* b4    = (const float*)d_in[9];
    const float* beta  = (const float*)d_in[10];
    const float* gamma = (const float*)d_in[11];
    float* out = (float*)d_out;

    mlp_kernel<<<(T_N + 255) / 256, 256>>>(t, w1, b1, w2, b2, w3, b3, w4, b4);
    scan_kernel<<<B_N, 128>>>(t, y, beta, gamma, out);
}

// round 9
// speedup vs baseline: 2.8916x; 2.8916x over previous
#include <cuda_runtime.h>

#define T_N 1024
#define B_N 256
#define H_N 20
#define B3  (B_N * 3)
#define OFF (T_N * B3)

__device__ float g_me[T_N];

// ---------------------------------------------------------------------------
// Kernel A: me[i] = sigmoid(MLP(t[i]))
// ---------------------------------------------------------------------------
__device__ __forceinline__ float tanh_fast(float x) {
    float e = __expf(2.0f * x);
    return 1.0f - 2.0f / (e + 1.0f);
}

__global__ void mlp_kernel(const float* __restrict__ t,
                           const float* __restrict__ w1, const float* __restrict__ b1,
                           const float* __restrict__ w2, const float* __restrict__ b2,
                           const float* __restrict__ w3, const float* __restrict__ b3,
                           const float* __restrict__ w4, const float* __restrict__ b4) {
    int i = blockIdx.x * blockDim.x + threadIdx.x;
    if (i >= T_N) return;
    float tv = t[i];

    float h1[H_N], h2[H_N];
    #pragma unroll
    for (int o = 0; o < H_N; o++)
        h1[o] = tanh_fast(tv * w1[o] + b1[o]);

    #pragma unroll
    for (int o = 0; o < H_N; o++) {
        float acc = b2[o];
        #pragma unroll
        for (int m = 0; m < H_N; m++)
            acc += h1[m] * w2[m * H_N + o];
        h2[o] = tanh_fast(acc);
    }

    #pragma unroll
    for (int o = 0; o < H_N; o++) {
        float acc = b3[o];
        #pragma unroll
        for (int m = 0; m < H_N; m++)
            acc += h2[m] * w3[m * H_N + o];
        h1[o] = tanh_fast(acc);
    }

    float acc = b4[0];
    #pragma unroll
    for (int m = 0; m < H_N; m++)
        acc += h1[m] * w4[m];

    g_me[i] = 1.0f / (1.0f + __expf(-acc));
}

// ---------------------------------------------------------------------------
// Kernel B: one CTA (192 thr = 6 warps) per batch element.
//  role 0      : scalar stepper. 16-slot register ring of near-field
//                accumulators; branch-free, shuffle-free, STG-free inner loop.
//  roles 1..4  : far-field helpers: Pf[n] = dt * sum_{k<8i} rs[n-k]*Ih[k]
//                for the NEXT interval's 8 targets, one interval ahead.
//  role 5      : writer: flushes staged outputs (prev interval) to global.
// rs[d] = me[T-d];  integ_n = dt * sum_{k<n} rs[n-k]*Ih[k].
// ---------------------------------------------------------------------------

#define STEP(nv, PHI, SLOT) {                                               \
    const int n_ = (nv);                                                    \
    const float integ = fmaf(dt, a[SLOT], Pf[n_]);                          \
    const float bSI = beta * S * I;                                         \
    const float gI  = gamma * I;                                            \
    const float d0 = integ - bSI;                                           \
    const float d1 = bSI - gI;                                              \
    const float d2 = gI - integ;                                            \
    S = fmaf(d0, dt, S);                                                    \
    I = fmaf(d1, dt, I);                                                    \
    R = fmaf(d2, dt, R);                                                    \
    if (lane0) Ih[n_] = I;                                                  \
    if (lane0) { stg[PHI][0] = make_float4(S, I, R, d0);                    \
                 stg[PHI][1] = make_float4(d1, d2, 0.f, 0.f); }             \
    _Pragma("unroll")                                                       \
    for (int d_ = 1; d_ <= 15 - (PHI); ++d_) {                              \
        const int s_ = ((SLOT) + d_) & 15;                                  \
        if ((PHI) == 0 && d_ >= 8) a[s_] = rsr[d_] * I;                     \
        else                       a[s_] = fmaf(rsr[d_], I, a[s_]);         \
    }                                                                       \
}

#define INTERVAL8(n0, RB)                                                   \
    STEP((n0) + 0, 0, ((RB) + 0))                                           \
    STEP((n0) + 1, 1, ((RB) + 1))                                           \
    STEP((n0) + 2, 2, ((RB) + 2))                                           \
    STEP((n0) + 3, 3, ((RB) + 3))                                           \
    STEP((n0) + 4, 4, ((RB) + 4))                                           \
    STEP((n0) + 5, 5, ((RB) + 5))                                           \
    STEP((n0) + 6, 6, ((RB) + 6))                                           \
    STEP((n0) + 7, 7, ((RB) + 7))

__global__ void __launch_bounds__(192) scan_kernel(
    const float* __restrict__ t,
    const float* __restrict__ y,
    const float* __restrict__ beta_p,
    const float* __restrict__ gamma_p,
    float* __restrict__ out) {

    __shared__ float rs[T_N];
    __shared__ float Ih[T_N];
    __shared__ float Pf[T_N];
    __shared__ float4 stage[2][8][2];

    const int b    = blockIdx.x;
    const int tid  = threadIdx.x;
    const int warp = tid >> 5;
    const int lane = tid & 31;
    // rotate roles so co-resident CTAs' steppers don't share an SMSP
    const int role = (warp + 6 - (b & 3)) % 6;
    const bool lane0 = (lane == 0);

    for (int i = tid; i < T_N; i += 192)
        rs[i] = (i == 0) ? 0.0f : g_me[T_N - i];
    if (tid < 16) Pf[tid] = 0.0f;   // intervals 0-1 have no far field

    const float dt    = t[0] - t[1];
    const float beta  = beta_p[0];
    const float gamma = gamma_p[0];
    const int   b3    = b * 3;

    // stepper registers (dead in other roles)
    float a[16];
    float rsr[16];
    float S = 0.f, I = 0.f, R = 0.f;
    if (role == 0) {
        #pragma unroll
        for (int s = 0; s < 16; s++) a[s] = 0.0f;
        S = y[b3 + 0];
        I = y[b3 + 1];
        R = y[b3 + 2];
    }
    __syncthreads();
    if (role == 0) {
        #pragma unroll
        for (int d = 1; d <= 15; d++) rsr[d] = rs[d];
    }

    for (int i = 0; i < 128; ++i) {
        if (role == 0) {
            float4 (*stg)[2] = stage[i & 1];
            if (i == 0) {
                // n = 0: emit initial state + trailing zero diff, seed scatter
                if (lane0) {
                    Ih[0] = I;
                    out[b3 + 0] = S; out[b3 + 1] = I; out[b3 + 2] = R;
                    const int zb = OFF + (T_N - 1) * B3 + b3;
                    out[zb + 0] = 0.0f; out[zb + 1] = 0.0f; out[zb + 2] = 0.0f;
                }
                #pragma unroll
                for (int d = 1; d <= 15; d++) a[d & 15] = rsr[d] * I;
                STEP(1, 1, 1) STEP(2, 2, 2) STEP(3, 3, 3) STEP(4, 4, 4)
                STEP(5, 5, 5) STEP(6, 6, 6) STEP(7, 7, 7)
            } else if (i & 1) {
                INTERVAL8(8 * i, 8)
            } else {
                INTERVAL8(8 * i, 0)
            }
        } else if (role <= 4) {
            // far-field for next interval's targets [8i+8, 8i+15]
            const int h  = role - 1;            // 0..3
            const int T0 = 8 * i + 8 + 2 * h;
            if (T0 < T_N) {
                const int K = 8 * i;
                float a0 = 0.f, a1 = 0.f;
                #pragma unroll 4
                for (int k = lane; k < K; k += 32) {
                    const float ih = Ih[k];
                    a0 = fmaf(rs[T0 - k],     ih, a0);
                    a1 = fmaf(rs[T0 + 1 - k], ih, a1);
                }
                #pragma unroll
                for (int s = 16; s > 0; s >>= 1) {
                    a0 += __shfl_xor_sync(0xffffffffu, a0, s);
                    a1 += __shfl_xor_sync(0xffffffffu, a1, s);
                }
                if (lane0) { Pf[T0] = dt * a0; Pf[T0 + 1] = dt * a1; }
            }
        } else {
            // writer: flush previous interval's staged outputs
            if (i >= 1 && lane < 24) {
                const int j  = i - 1;
                const int ph = lane / 3;
                const int c  = lane % 3;
                const int n  = 8 * j + ph;
                if (n >= 1) {
                    const float* sp = (const float*)&stage[j & 1][ph][0];
                    out[n * B3 + b3 + c]                 = sp[c];
                    out[OFF + (n - 1) * B3 + b3 + c]     = sp[3 + c];   // d0,d1,d2
                }
            }
        }
        __syncthreads();
    }

    // final flush of interval 127
    if (role == 5 && lane < 24) {
        const int ph = lane / 3;
        const int c  = lane % 3;
        const int n  = 8 * 127 + ph;
        const float* sp = (const float*)&stage[127 & 1][ph][0];
        out[n * B3 + b3 + c]             = sp[c];
        out[OFF + (n - 1) * B3 + b3 + c] = sp[3 + c];   // d0,d1,d2
    }
}

// ---------------------------------------------------------------------------
// Launch
// ---------------------------------------------------------------------------
extern "C" void kernel_launch(void* const* d_in, const int* in_sizes, int n_in,
                              void* d_out, int out_size) {
    const float* t     = (const float*)d_in[0];
    const float* y     = (const float*)d_in[1];
    const float* w1    = (const float*)d_in[2];
    const float* b1    = (const float*)d_in[3];
    const float* w2    = (const float*)d_in[4];
    const float* b2    = (const float*)d_in[5];
    const float* w3    = (const float*)d_in[6];
    const float* b3    = (const float*)d_in[7];
    const float* w4    = (const float*)d_in[8];
    const float* b4    = (const float*)d_in[9];
    const float* beta  = (const float*)d_in[10];
    const float* gamma = (const float*)d_in[11];
    float* out = (float*)d_out;

    mlp_kernel<<<(T_N + 127) / 128, 128>>>(t, w1, b1, w2, b2, w3, b3, w4, b4);
    scan_kernel<<<B_N, 192>>>(t, y, beta, gamma, out);
}

// round 11
// speedup vs baseline: 4.1401x; 1.4317x over previous
#include <cuda_runtime.h>

#define T_N 1024
#define B_N 256
#define H_N 20
#define B3  (B_N * 3)
#define OFF (T_N * B3)

__device__ float g_me[T_N];

// ---------------------------------------------------------------------------
// Kernel A: me[i] = sigmoid(MLP(t[i]))
// ---------------------------------------------------------------------------
__device__ __forceinline__ float tanh_fast(float x) {
    float e = __expf(2.0f * x);
    return 1.0f - 2.0f / (e + 1.0f);
}

__global__ void mlp_kernel(const float* __restrict__ t,
                           const float* __restrict__ w1, const float* __restrict__ b1,
                           const float* __restrict__ w2, const float* __restrict__ b2,
                           const float* __restrict__ w3, const float* __restrict__ b3,
                           const float* __restrict__ w4, const float* __restrict__ b4) {
    int i = blockIdx.x * blockDim.x + threadIdx.x;
    if (i >= T_N) return;
    float tv = t[i];

    float h1[H_N], h2[H_N];
    #pragma unroll
    for (int o = 0; o < H_N; o++)
        h1[o] = tanh_fast(tv * w1[o] + b1[o]);

    #pragma unroll
    for (int o = 0; o < H_N; o++) {
        float acc = b2[o];
        #pragma unroll
        for (int m = 0; m < H_N; m++)
            acc += h1[m] * w2[m * H_N + o];
        h2[o] = tanh_fast(acc);
    }

    #pragma unroll
    for (int o = 0; o < H_N; o++) {
        float acc = b3[o];
        #pragma unroll
        for (int m = 0; m < H_N; m++)
            acc += h2[m] * w3[m * H_N + o];
        h1[o] = tanh_fast(acc);
    }

    float acc = b4[0];
    #pragma unroll
    for (int m = 0; m < H_N; m++)
        acc += h1[m] * w4[m];

    g_me[i] = 1.0f / (1.0f + __expf(-acc));
}

// ---------------------------------------------------------------------------
// Kernel B: one CTA (192 thr = 6 warps) per batch element.
//  role 0      : scalar stepper (16-slot register ring, branch/shuffle/STG-free)
//  roles 1..4  : far-field helpers. float4 k-chunks x 8 targets via a 12-float
//                rs register window; transpose-reduce; atomicAdd into Pf.
//  role 5      : writer (flush staged outputs; zero Pf two intervals ahead)
// rs[d] = me[T-d];  integ_n = dt * sum_{k<n} rs[n-k]*Ih[k].
// ---------------------------------------------------------------------------

#define STEP(nv, PHI, SLOT, PFV) {                                          \
    const int n_ = (nv);                                                    \
    const float integ = fmaf(dt, a[SLOT], (PFV));                           \
    const float bSI = beta * S * I;                                         \
    const float gI  = gamma * I;                                            \
    const float d0 = integ - bSI;                                           \
    const float d1 = bSI - gI;                                              \
    const float d2 = gI - integ;                                            \
    S = fmaf(d0, dt, S);                                                    \
    I = fmaf(d1, dt, I);                                                    \
    R = fmaf(d2, dt, R);                                                    \
    if (lane0) Ih[n_] = I;                                                  \
    if (lane0) { stg[PHI][0] = make_float4(S, I, R, d0);                    \
                 stg[PHI][1] = make_float4(d1, d2, 0.f, 0.f); }             \
    _Pragma("unroll")                                                       \
    for (int d_ = 1; d_ <= 15 - (PHI); ++d_) {                              \
        const int s_ = ((SLOT) + d_) & 15;                                  \
        if ((PHI) == 0 && d_ >= 8) a[s_] = rsr[d_] * I;                     \
        else                       a[s_] = fmaf(rsr[d_], I, a[s_]);         \
    }                                                                       \
}

#define INTERVAL8(n0, RB)                                                   \
    STEP((n0) + 0, 0, ((RB) + 0), pfa.x)                                    \
    STEP((n0) + 1, 1, ((RB) + 1), pfa.y)                                    \
    STEP((n0) + 2, 2, ((RB) + 2), pfa.z)                                    \
    STEP((n0) + 3, 3, ((RB) + 3), pfa.w)                                    \
    STEP((n0) + 4, 4, ((RB) + 4), pfb.x)                                    \
    STEP((n0) + 5, 5, ((RB) + 5), pfb.y)                                    \
    STEP((n0) + 6, 6, ((RB) + 6), pfb.z)                                    \
    STEP((n0) + 7, 7, ((RB) + 7), pfb.w)

__global__ void __launch_bounds__(192) scan_kernel(
    const float* __restrict__ t,
    const float* __restrict__ y,
    const float* __restrict__ beta_p,
    const float* __restrict__ gamma_p,
    float* __restrict__ out) {

    __shared__ __align__(16) float rs[T_N];
    __shared__ __align__(16) float Ih[T_N];
    __shared__ __align__(16) float Pf[T_N];
    __shared__ float  Ps[4][8][33];     // helper transpose-reduce scratch
    __shared__ float4 stage[2][8][2];

    const int b    = blockIdx.x;
    const int tid  = threadIdx.x;
    const int warp = tid >> 5;
    const int lane = tid & 31;
    const int role = (warp + 6 - (b & 3)) % 6;
    const bool lane0 = (lane == 0);

    for (int i = tid; i < T_N; i += 192)
        rs[i] = (i == 0) ? 0.0f : g_me[T_N - i];
    if (tid < 16) Pf[tid] = 0.0f;   // intervals 0-1 have no far field

    const float dt    = t[0] - t[1];
    const float beta  = beta_p[0];
    const float gamma = gamma_p[0];
    const int   b3    = b * 3;

    float a[16];
    float rsr[16];
    float S = 0.f, I = 0.f, R = 0.f;
    if (role == 0) {
        #pragma unroll
        for (int s = 0; s < 16; s++) a[s] = 0.0f;
        S = y[b3 + 0];
        I = y[b3 + 1];
        R = y[b3 + 2];
    }
    __syncthreads();
    if (role == 0) {
        #pragma unroll
        for (int d = 1; d <= 15; d++) rsr[d] = rs[d];
    }

    for (int i = 0; i < 128; ++i) {
        if (role == 0) {
            float4 (*stg)[2] = stage[i & 1];
            if (i == 0) {
                if (lane0) {
                    Ih[0] = I;
                    out[b3 + 0] = S; out[b3 + 1] = I; out[b3 + 2] = R;
                    const int zb = OFF + (T_N - 1) * B3 + b3;
                    out[zb + 0] = 0.0f; out[zb + 1] = 0.0f; out[zb + 2] = 0.0f;
                }
                #pragma unroll
                for (int d = 1; d <= 15; d++) a[d & 15] = rsr[d] * I;
                STEP(1, 1, 1, 0.0f) STEP(2, 2, 2, 0.0f) STEP(3, 3, 3, 0.0f)
                STEP(4, 4, 4, 0.0f) STEP(5, 5, 5, 0.0f) STEP(6, 6, 6, 0.0f)
                STEP(7, 7, 7, 0.0f)
            } else {
                const float4 pfa = *(const float4*)&Pf[8 * i];
                const float4 pfb = *(const float4*)&Pf[8 * i + 4];
                if (i & 1) { INTERVAL8(8 * i, 8) }
                else       { INTERVAL8(8 * i, 0) }
            }
        } else if (role <= 4) {
            // far field for targets [8(i+1), 8(i+1)+7] over k < 8i
            const int h  = role - 1;
            const int T0 = 8 * i + 8;
            if (i >= 1 && T0 < T_N) {
                const int nch = 2 * i;           // float4 chunks of k
                float acc[8];
                #pragma unroll
                for (int tt = 0; tt < 8; tt++) acc[tt] = 0.0f;
                for (int c = h * 32 + lane; c < nch; c += 128) {
                    const int k0 = c << 2;
                    const float4 ih = *(const float4*)&Ih[k0];
                    const float* wp = &rs[T0 - k0 - 4];
                    float w[12];
                    *(float4*)&w[0] = *(const float4*)&wp[0];
                    *(float4*)&w[4] = *(const float4*)&wp[4];
                    *(float4*)&w[8] = *(const float4*)&wp[8];
                    #pragma unroll
                    for (int tt = 0; tt < 8; tt++) {
                        float s0 = fmaf(w[tt + 4], ih.x, acc[tt]);
                        s0 = fmaf(w[tt + 3], ih.y, s0);
                        s0 = fmaf(w[tt + 2], ih.z, s0);
                        acc[tt] = fmaf(w[tt + 1], ih.w, s0);
                    }
                }
                // transpose-reduce: 32 lanes x 8 targets -> 8 sums
                #pragma unroll
                for (int tt = 0; tt < 8; tt++) Ps[h][tt][lane] = acc[tt];
                __syncwarp();
                const int ttr = lane >> 2, pp = lane & 3;
                const float* q = &Ps[h][ttr][pp * 8];
                float s0 = ((q[0] + q[1]) + (q[2] + q[3]))
                         + ((q[4] + q[5]) + (q[6] + q[7]));
                s0 += __shfl_xor_sync(0xffffffffu, s0, 1);
                s0 += __shfl_xor_sync(0xffffffffu, s0, 2);
                if (pp == 0) atomicAdd(&Pf[T0 + ttr], dt * s0);
            }
        } else {
            // writer: zero Pf two intervals ahead; flush prev interval outputs
            const int z = 8 * i + 16;
            if (z < T_N && lane >= 24 && lane < 32) Pf[z + (lane - 24)] = 0.0f;
            if (i >= 1 && lane < 24) {
                const int j  = i - 1;
                const int ph = lane / 3;
                const int c  = lane % 3;
                const int n  = 8 * j + ph;
                if (n >= 1) {
                    const float* sp = (const float*)&stage[j & 1][ph][0];
                    out[n * B3 + b3 + c]             = sp[c];
                    out[OFF + (n - 1) * B3 + b3 + c] = sp[3 + c];
                }
            }
        }
        __syncthreads();
    }

    // final flush of interval 127
    if (role == 5 && lane < 24) {
        const int ph = lane / 3;
        const int c  = lane % 3;
        const int n  = 8 * 127 + ph;
        const float* sp = (const float*)&stage[127 & 1][ph][0];
        out[n * B3 + b3 + c]             = sp[c];
        out[OFF + (n - 1) * B3 + b3 + c] = sp[3 + c];
    }
}

// ---------------------------------------------------------------------------
// Launch
// ---------------------------------------------------------------------------
extern "C" void kernel_launch(void* const* d_in, const int* in_sizes, int n_in,
                              void* d_out, int out_size) {
    const float* t     = (const float*)d_in[0];
    const float* y     = (const float*)d_in[1];
    const float* w1    = (const float*)d_in[2];
    const float* b1    = (const float*)d_in[3];
    const float* w2    = (const float*)d_in[4];
    const float* b2    = (const float*)d_in[5];
    const float* w3    = (const float*)d_in[6];
    const float* b3    = (const float*)d_in[7];
    const float* w4    = (const float*)d_in[8];
    const float* b4    = (const float*)d_in[9];
    const float* beta  = (const float*)d_in[10];
    const float* gamma = (const float*)d_in[11];
    float* out = (float*)d_out;

    mlp_kernel<<<(T_N + 127) / 128, 128>>>(t, w1, b1, w2, b2, w3, b3, w4, b4);
    scan_kernel<<<B_N, 192>>>(t, y, beta, gamma, out);
}